// round 3
// baseline (speedup 1.0000x reference)
#include <cuda_runtime.h>

// SegmenterTorch (WOLA, HOP=512, SEG=1024, sqrt-Hann).
// Interior gain == sin^2+cos^2 == 1  ->  pure 512 MB HBM stream; only the
// first/last 512 samples of each of the 16 rows need the window product.
// This round: 256-bit global ld/st (sm_103a ld/st.global.v8.f32) to present
// 1 KB contiguous bursts per warp access to the memory system.

#define HOPV 512
#define NSAMPLES 4194304            // floats per batch row (power of 2)
#define NSEG 8191
#define INTERIOR_END (NSEG * HOPV)  // 4193792

#define THREADS 256
#define VPT 8                        // vec8 (32B) chunks per thread
#define PER_BLOCK (THREADS * VPT)    // 2048 vec8 = 16384 floats = 64 KB per CTA

__device__ __forceinline__ void ldg256_cs(const float* p, float* r) {
    asm volatile(
        "ld.global.cs.v8.f32 {%0,%1,%2,%3,%4,%5,%6,%7}, [%8];"
        : "=f"(r[0]), "=f"(r[1]), "=f"(r[2]), "=f"(r[3]),
          "=f"(r[4]), "=f"(r[5]), "=f"(r[6]), "=f"(r[7])
        : "l"(p));
}

__device__ __forceinline__ void stg256_cs(float* p, const float* r) {
    asm volatile(
        "st.global.cs.v8.f32 [%0], {%1,%2,%3,%4,%5,%6,%7,%8};"
        :: "l"(p),
           "f"(r[0]), "f"(r[1]), "f"(r[2]), "f"(r[3]),
           "f"(r[4]), "f"(r[5]), "f"(r[6]), "f"(r[7])
        : "memory");
}

__global__ __launch_bounds__(THREADS)
void wola_stream256_kernel(const float* __restrict__ x,
                           const float* __restrict__ aw,
                           const float* __restrict__ sw,
                           float* __restrict__ out) {
    // vec8 index; exact-division grid, no bounds checks needed.
    const int base = blockIdx.x * PER_BLOCK + threadIdx.x;

#pragma unroll
    for (int it = 0; it < VPT; ++it) {
        const int v    = base + it * THREADS;
        const int n    = v << 3;               // float index (fits int: < 2^26)
        const int nrow = n & (NSAMPLES - 1);   // index within batch row

        float r[8];
        ldg256_cs(x + n, r);

        if (nrow < HOPV || nrow >= INTERIOR_END) {
            // Edge: exactly one covering frame.
            //   head: gain = aw[m]*sw[m]; tail: gain = aw[m+512]*sw[m+512]
            const int m   = nrow & (HOPV - 1);            // 8-aligned
            const int off = (nrow < HOPV) ? m : (m + HOPV);
#pragma unroll
            for (int i = 0; i < 8; ++i)
                r[i] *= aw[off + i] * sw[off + i];
        }
        // Interior: gain == 1, r unchanged.
        stg256_cs(out + n, r);
    }
}

extern "C" void kernel_launch(void* const* d_in, const int* in_sizes, int n_in,
                              void* d_out, int out_size) {
    const float* x  = (const float*)d_in[0];   // [16, 4194304] f32
    const float* aw = (const float*)d_in[1];   // [1024] f32
    const float* sw = (const float*)d_in[2];   // [1024] f32
    float*       o  = (float*)d_out;

    const int nvec8  = out_size >> 3;          // 8,388,608
    const int blocks = nvec8 / PER_BLOCK;      // 4096 (exact)

    wola_stream256_kernel<<<blocks, THREADS>>>(x, aw, sw, o);
}

// round 4
// speedup vs baseline: 1.0252x; 1.0252x over previous
#include <cuda_runtime.h>

// SegmenterTorch (WOLA, HOP=512, SEG=1024, sqrt-Hann).
// Interior gain == sin^2+cos^2 == 1  ->  pure 512 MB HBM stream; only the
// first/last 512 samples of each of the 16 rows need the window product.
// Round 4: explicitly front-batch 4 independent 256-bit loads per thread
// before storing (MLP=4 per warp instead of ~1), to keep more read requests
// in flight across the store drain and cut DRAM read/write turnaround
// exposure.

#define HOPV 512
#define NSAMPLES 4194304            // floats per batch row (power of 2)
#define NSEG 8191
#define INTERIOR_END (NSEG * HOPV)  // 4193792

#define THREADS 256
#define GROUPS 2
#define GSIZE 4                      // vec8 loads batched per group
#define VPT (GROUPS * GSIZE)         // 8 vec8 per thread
#define PER_BLOCK (THREADS * VPT)    // 2048 vec8 = 64 KB per CTA

__device__ __forceinline__ void ldg256_cs(const float* p, float* r) {
    asm volatile(
        "ld.global.cs.v8.f32 {%0,%1,%2,%3,%4,%5,%6,%7}, [%8];"
        : "=f"(r[0]), "=f"(r[1]), "=f"(r[2]), "=f"(r[3]),
          "=f"(r[4]), "=f"(r[5]), "=f"(r[6]), "=f"(r[7])
        : "l"(p));
}

__device__ __forceinline__ void stg256_cs(float* p, const float* r) {
    asm volatile(
        "st.global.cs.v8.f32 [%0], {%1,%2,%3,%4,%5,%6,%7,%8};"
        :: "l"(p),
           "f"(r[0]), "f"(r[1]), "f"(r[2]), "f"(r[3]),
           "f"(r[4]), "f"(r[5]), "f"(r[6]), "f"(r[7])
        : "memory");
}

__global__ __launch_bounds__(THREADS)
void wola_stream256_mlp_kernel(const float* __restrict__ x,
                               const float* __restrict__ aw,
                               const float* __restrict__ sw,
                               float* __restrict__ out) {
    const int base = blockIdx.x * PER_BLOCK + threadIdx.x;

#pragma unroll
    for (int g = 0; g < GROUPS; ++g) {
        const int v0 = base + g * (GSIZE * THREADS);

        // Phase 1: batch GSIZE independent 256-bit loads (128 B in flight).
        float r[GSIZE][8];
#pragma unroll
        for (int j = 0; j < GSIZE; ++j) {
            const int n = (v0 + j * THREADS) << 3;
            ldg256_cs(x + n, r[j]);
        }

        // Phase 2: (rare) edge gain, then stores.
#pragma unroll
        for (int j = 0; j < GSIZE; ++j) {
            const int n    = (v0 + j * THREADS) << 3;
            const int nrow = n & (NSAMPLES - 1);   // index within batch row

            if (nrow < HOPV || nrow >= INTERIOR_END) {
                // Edge: exactly one covering frame.
                //   head: gain = aw[m]*sw[m]; tail: aw[m+512]*sw[m+512]
                const int m   = nrow & (HOPV - 1);           // 8-aligned
                const int off = (nrow < HOPV) ? m : (m + HOPV);
#pragma unroll
                for (int i = 0; i < 8; ++i)
                    r[j][i] *= aw[off + i] * sw[off + i];
            }
            stg256_cs(out + n, r[j]);
        }
    }
}

extern "C" void kernel_launch(void* const* d_in, const int* in_sizes, int n_in,
                              void* d_out, int out_size) {
    const float* x  = (const float*)d_in[0];   // [16, 4194304] f32
    const float* aw = (const float*)d_in[1];   // [1024] f32
    const float* sw = (const float*)d_in[2];   // [1024] f32
    float*       o  = (float*)d_out;

    const int nvec8  = out_size >> 3;          // 8,388,608
    const int blocks = nvec8 / PER_BLOCK;      // 4096 (exact)

    wola_stream256_mlp_kernel<<<blocks, THREADS>>>(x, aw, sw, o);
}

// round 5
// speedup vs baseline: 1.0300x; 1.0047x over previous
#include <cuda_runtime.h>

// SegmenterTorch (WOLA, HOP=512, SEG=1024, sqrt-Hann).
// Interior gain == sin^2+cos^2 == 1  ->  pure 512 MB HBM stream; only the
// first/last 512 samples of each of the 16 rows need the window product.
// Round 5: front-batch 8 independent 256-bit loads per thread (256 B of
// reads in flight per thread) before the 8 stores — MLP=8 per the B300
// LDG latency model (lat = 577/MLP_eff + C). R4 showed dur and DRAM% track
// MLP, not occupancy.

#define HOPV 512
#define NSAMPLES 4194304            // floats per batch row (power of 2)
#define NSEG 8191
#define INTERIOR_END (NSEG * HOPV)  // 4193792

#define THREADS 256
#define GSIZE 8                      // vec8 loads batched per thread
#define PER_BLOCK (THREADS * GSIZE)  // 2048 vec8 = 64 KB per CTA

__device__ __forceinline__ void ldg256_cs(const float* p, float* r) {
    asm volatile(
        "ld.global.cs.v8.f32 {%0,%1,%2,%3,%4,%5,%6,%7}, [%8];"
        : "=f"(r[0]), "=f"(r[1]), "=f"(r[2]), "=f"(r[3]),
          "=f"(r[4]), "=f"(r[5]), "=f"(r[6]), "=f"(r[7])
        : "l"(p));
}

__device__ __forceinline__ void stg256_cs(float* p, const float* r) {
    asm volatile(
        "st.global.cs.v8.f32 [%0], {%1,%2,%3,%4,%5,%6,%7,%8};"
        :: "l"(p),
           "f"(r[0]), "f"(r[1]), "f"(r[2]), "f"(r[3]),
           "f"(r[4]), "f"(r[5]), "f"(r[6]), "f"(r[7])
        : "memory");
}

__global__ __launch_bounds__(THREADS)
void wola_stream256_mlp8_kernel(const float* __restrict__ x,
                                const float* __restrict__ aw,
                                const float* __restrict__ sw,
                                float* __restrict__ out) {
    const int base = blockIdx.x * PER_BLOCK + threadIdx.x;

    // Phase 1: 8 independent 256-bit loads, all issued before any store.
    float r[GSIZE][8];
#pragma unroll
    for (int j = 0; j < GSIZE; ++j) {
        const int n = (base + j * THREADS) << 3;
        ldg256_cs(x + n, r[j]);
    }

    // Phase 2: (rare) edge gain, then stores.
#pragma unroll
    for (int j = 0; j < GSIZE; ++j) {
        const int n    = (base + j * THREADS) << 3;
        const int nrow = n & (NSAMPLES - 1);   // index within batch row

        if (nrow < HOPV || nrow >= INTERIOR_END) {
            // Edge: exactly one covering frame.
            //   head: gain = aw[m]*sw[m]; tail: aw[m+512]*sw[m+512]
            const int m   = nrow & (HOPV - 1);           // 8-aligned
            const int off = (nrow < HOPV) ? m : (m + HOPV);
#pragma unroll
            for (int i = 0; i < 8; ++i)
                r[j][i] *= aw[off + i] * sw[off + i];
        }
        stg256_cs(out + n, r[j]);
    }
}

extern "C" void kernel_launch(void* const* d_in, const int* in_sizes, int n_in,
                              void* d_out, int out_size) {
    const float* x  = (const float*)d_in[0];   // [16, 4194304] f32
    const float* aw = (const float*)d_in[1];   // [1024] f32
    const float* sw = (const float*)d_in[2];   // [1024] f32
    float*       o  = (float*)d_out;

    const int nvec8  = out_size >> 3;          // 8,388,608
    const int blocks = nvec8 / PER_BLOCK;      // 4096 (exact)

    wola_stream256_mlp8_kernel<<<blocks, THREADS>>>(x, aw, sw, o);
}